// round 5
// baseline (speedup 1.0000x reference)
#include <cuda_runtime.h>
#include <cuda_fp16.h>

#define NN 100000
#define NE 1600000
#define F_IN 64
#define F_HID 64
#define F_OUT 32

#define SCAN_BLK 1024
#define SCAN_NBLK ((NN + SCAN_BLK - 1) / SCAN_BLK)   // 98

// ---- scratch (device globals; no allocation allowed) ----
__device__ __align__(16) __half g_h1h[NN * F_HID];  // x@W1 in fp16 (row = 128B)
__device__ __align__(16) __half g_h2h[NN * F_OUT];  // layer-2 pre-agg in fp16 (row = 64B)
__device__ float g_agg1[NN * F_HID];
__device__ float g_outnorm[NN];
__device__ float g_innorm [NN];
__device__ int   g_degs[NN];
__device__ int   g_degd[NN];
__device__ int   g_rowptr[NN + 1];
__device__ int   g_cursor[NN];
__device__ int   g_csr_src[NE];
__device__ int   g_blocksums[SCAN_NBLK];

// ---- zero degree counters ----
__global__ void k_zero() {
    int i = blockIdx.x * blockDim.x + threadIdx.x;
    if (i < NN) { g_degs[i] = 0; g_degd[i] = 0; }
}

// ---- degrees ----
__global__ void k_deg(const int* __restrict__ src, const int* __restrict__ dst) {
    int e = blockIdx.x * blockDim.x + threadIdx.x;
    if (e < NE) {
        atomicAdd(&g_degs[src[e]], 1);
        atomicAdd(&g_degd[dst[e]], 1);
    }
}

// ---- scan stage 1: per-block exclusive scan of dst-degrees ----
__global__ __launch_bounds__(256) void k_scan1() {
    __shared__ int wsum[8];
    int t = threadIdx.x, b = blockIdx.x;
    int base = b * SCAN_BLK + t * 4;
    int v0 = 0, v1 = 0, v2 = 0, v3 = 0;
    if (base + 0 < NN) v0 = g_degd[base + 0];
    if (base + 1 < NN) v1 = g_degd[base + 1];
    if (base + 2 < NN) v2 = g_degd[base + 2];
    if (base + 3 < NN) v3 = g_degd[base + 3];
    int sum = v0 + v1 + v2 + v3;

    int lane = t & 31, wid = t >> 5;
    int x = sum;
    #pragma unroll
    for (int o = 1; o < 32; o <<= 1) {
        int y = __shfl_up_sync(0xffffffffu, x, o);
        if (lane >= o) x += y;
    }
    if (lane == 31) wsum[wid] = x;
    __syncthreads();
    if (wid == 0 && lane < 8) {
        int w = wsum[lane];
        #pragma unroll
        for (int o = 1; o < 8; o <<= 1) {
            int y = __shfl_up_sync(0x000000ffu, w, o);
            if (lane >= o) w += y;
        }
        wsum[lane] = w;
    }
    __syncthreads();
    int incl = x + (wid > 0 ? wsum[wid - 1] : 0);
    int excl = incl - sum;

    if (base + 0 < NN) g_rowptr[base + 0] = excl;
    if (base + 1 < NN) g_rowptr[base + 1] = excl + v0;
    if (base + 2 < NN) g_rowptr[base + 2] = excl + v0 + v1;
    if (base + 3 < NN) g_rowptr[base + 3] = excl + v0 + v1 + v2;
    if (t == 255) g_blocksums[b] = incl;
}

// ---- scan stage 2: exclusive scan of the 98 block sums ----
__global__ __launch_bounds__(128) void k_scan2() {
    __shared__ int wsum[4];
    int t = threadIdx.x;
    int v = (t < SCAN_NBLK) ? g_blocksums[t] : 0;
    int lane = t & 31, wid = t >> 5;
    int x = v;
    #pragma unroll
    for (int o = 1; o < 32; o <<= 1) {
        int y = __shfl_up_sync(0xffffffffu, x, o);
        if (lane >= o) x += y;
    }
    if (lane == 31) wsum[wid] = x;
    __syncthreads();
    if (wid == 0 && lane < 4) {
        int w = wsum[lane];
        #pragma unroll
        for (int o = 1; o < 4; o <<= 1) {
            int y = __shfl_up_sync(0x0000000fu, w, o);
            if (lane >= o) w += y;
        }
        wsum[lane] = w;
    }
    __syncthreads();
    int incl = x + (wid > 0 ? wsum[wid - 1] : 0);
    if (t < SCAN_NBLK) g_blocksums[t] = incl - v;
}

// ---- scan stage 3 + norms ----
__global__ void k_scan3norm() {
    int i = blockIdx.x * blockDim.x + threadIdx.x;
    if (i < NN) {
        int r = g_rowptr[i] + g_blocksums[i >> 10];
        g_rowptr[i] = r;
        g_cursor[i] = r;
        int ds = g_degs[i]; if (ds < 1) ds = 1;
        int dd = g_degd[i]; if (dd < 1) dd = 1;
        g_outnorm[i] = rsqrtf((float)ds);
        g_innorm[i]  = rsqrtf((float)dd);
    }
    if (i == 0) g_rowptr[NN] = NE;
}

// ---- bucket: CSR adjacency (src ids grouped by dst) ----
__global__ void k_bucket(const int* __restrict__ src, const int* __restrict__ dst) {
    int e = blockIdx.x * blockDim.x + threadIdx.x;
    if (e < NE) {
        int pos = atomicAdd(&g_cursor[dst[e]], 1);
        g_csr_src[pos] = src[e];
    }
}

// ---- GEMM1: h1 = x @ W1 -> fp16 (norm scaling deferred to gather1) ----
__global__ __launch_bounds__(256) void k_gemm1(const float* __restrict__ x,
                                               const float* __restrict__ W1) {
    __shared__ float Ws[64 * 64];
    __shared__ float xs[64][68];
    int tid = threadIdx.x;
    int nb  = blockIdx.x * 64;

    #pragma unroll
    for (int r = 0; r < 4; r++) {
        int idx = tid + r * 256;
        reinterpret_cast<float4*>(Ws)[idx] =
            reinterpret_cast<const float4*>(W1)[idx];
    }
    // Staging: warp covers 32 consecutive n for fixed k4 -> conflict-free smem writes
    #pragma unroll
    for (int r = 0; r < 4; r++) {
        int idx = tid + r * 256;          // 0..1023
        int k4 = idx >> 6;                // 0..15
        int n  = idx & 63;                // 0..63
        int node = nb + n;
        float4 v = make_float4(0.f, 0.f, 0.f, 0.f);
        if (node < NN)
            v = reinterpret_cast<const float4*>(x)[node * 16 + k4];
        xs[k4 * 4 + 0][n] = v.x;
        xs[k4 * 4 + 1][n] = v.y;
        xs[k4 * 4 + 2][n] = v.z;
        xs[k4 * 4 + 3][n] = v.w;
    }
    __syncthreads();

    int tx = tid & 15;
    int ty = tid >> 4;
    float acc[4][4] = {};
    #pragma unroll
    for (int k = 0; k < 64; k++) {
        float4 wv = *reinterpret_cast<const float4*>(&Ws[k * 64 + tx * 4]);
        float4 xv = *reinterpret_cast<const float4*>(&xs[k][ty * 4]);
        float xr[4] = {xv.x, xv.y, xv.z, xv.w};
        float wr[4] = {wv.x, wv.y, wv.z, wv.w};
        #pragma unroll
        for (int i = 0; i < 4; i++)
            #pragma unroll
            for (int j = 0; j < 4; j++)
                acc[i][j] += xr[i] * wr[j];
    }
    #pragma unroll
    for (int i = 0; i < 4; i++) {
        int node = nb + ty * 4 + i;
        if (node < NN) {
            __half2 p0 = __floats2half2_rn(acc[i][0], acc[i][1]);
            __half2 p1 = __floats2half2_rn(acc[i][2], acc[i][3]);
            uint2 u;
            u.x = *reinterpret_cast<unsigned*>(&p0);
            u.y = *reinterpret_cast<unsigned*>(&p1);
            reinterpret_cast<uint2*>(g_h1h)[node * 16 + tx] = u;
        }
    }
}

// ---- gather1: agg1[n] = sum_s h1[s]*outnorm[s]. Warp/node, half2 loads (128B row). ----
__global__ __launch_bounds__(256) void k_gather1() {
    int w = (blockIdx.x * 256 + threadIdx.x) >> 5;
    int lane = threadIdx.x & 31;
    if (w >= NN) return;
    int beg = g_rowptr[w], end = g_rowptr[w + 1];
    const __half2* h1 = reinterpret_cast<const __half2*>(g_h1h);

    float2 a0 = {0.f,0.f}, a1 = a0, a2 = a0, a3 = a0;
    for (int c = beg; c < end; c += 32) {
        int idx = c + lane;
        int sreg = 0; float snorm = 0.f;
        if (idx < end) { sreg = g_csr_src[idx]; snorm = g_outnorm[sreg]; }
        int n = end - c; if (n > 32) n = 32;
        int j = 0;
        for (; j + 4 <= n; j += 4) {
            int   s0 = __shfl_sync(0xffffffffu, sreg,  j + 0);
            int   s1 = __shfl_sync(0xffffffffu, sreg,  j + 1);
            int   s2 = __shfl_sync(0xffffffffu, sreg,  j + 2);
            int   s3 = __shfl_sync(0xffffffffu, sreg,  j + 3);
            float o0 = __shfl_sync(0xffffffffu, snorm, j + 0);
            float o1 = __shfl_sync(0xffffffffu, snorm, j + 1);
            float o2 = __shfl_sync(0xffffffffu, snorm, j + 2);
            float o3 = __shfl_sync(0xffffffffu, snorm, j + 3);
            float2 v0 = __half22float2(h1[s0 * 32 + lane]);
            float2 v1 = __half22float2(h1[s1 * 32 + lane]);
            float2 v2 = __half22float2(h1[s2 * 32 + lane]);
            float2 v3 = __half22float2(h1[s3 * 32 + lane]);
            a0.x = fmaf(v0.x, o0, a0.x); a0.y = fmaf(v0.y, o0, a0.y);
            a1.x = fmaf(v1.x, o1, a1.x); a1.y = fmaf(v1.y, o1, a1.y);
            a2.x = fmaf(v2.x, o2, a2.x); a2.y = fmaf(v2.y, o2, a2.y);
            a3.x = fmaf(v3.x, o3, a3.x); a3.y = fmaf(v3.y, o3, a3.y);
        }
        for (; j < n; j++) {
            int   s = __shfl_sync(0xffffffffu, sreg,  j);
            float o = __shfl_sync(0xffffffffu, snorm, j);
            float2 v = __half22float2(h1[s * 32 + lane]);
            a0.x = fmaf(v.x, o, a0.x); a0.y = fmaf(v.y, o, a0.y);
        }
    }
    float2 r;
    r.x = (a0.x + a1.x) + (a2.x + a3.x);
    r.y = (a0.y + a1.y) + (a2.y + a3.y);
    reinterpret_cast<float2*>(g_agg1)[w * 32 + lane] = r;
}

// ---- Fused layer-1 epilogue + GEMM2 (64 -> 32) -> fp16 ----
__global__ __launch_bounds__(256) void k_gemm2(const float* __restrict__ W2,
                                               const float* __restrict__ b1) {
    __shared__ float Ws[64 * 32];
    __shared__ float xs[64][68];
    int tid = threadIdx.x;
    int nb  = blockIdx.x * 64;

    #pragma unroll
    for (int r = 0; r < 2; r++) {
        int idx = tid + r * 256;
        reinterpret_cast<float4*>(Ws)[idx] =
            reinterpret_cast<const float4*>(W2)[idx];
    }
    #pragma unroll
    for (int r = 0; r < 4; r++) {
        int idx = tid + r * 256;
        int k4 = idx >> 6;
        int n  = idx & 63;
        int node = nb + n;
        float4 v = make_float4(0.f, 0.f, 0.f, 0.f);
        if (node < NN) {
            v = reinterpret_cast<const float4*>(g_agg1)[node * 16 + k4];
            float in_n = g_innorm[node];
            float on   = g_outnorm[node];
            float4 bb  = reinterpret_cast<const float4*>(b1)[k4];
            v.x = fmaxf(fmaf(v.x, in_n, bb.x), 0.f) * on;
            v.y = fmaxf(fmaf(v.y, in_n, bb.y), 0.f) * on;
            v.z = fmaxf(fmaf(v.z, in_n, bb.z), 0.f) * on;
            v.w = fmaxf(fmaf(v.w, in_n, bb.w), 0.f) * on;
        }
        xs[k4 * 4 + 0][n] = v.x;
        xs[k4 * 4 + 1][n] = v.y;
        xs[k4 * 4 + 2][n] = v.z;
        xs[k4 * 4 + 3][n] = v.w;
    }
    __syncthreads();

    int tx = tid & 7;
    int ty = tid >> 3;
    float acc[2][4] = {};
    #pragma unroll
    for (int k = 0; k < 64; k++) {
        float4 wv = *reinterpret_cast<const float4*>(&Ws[k * 32 + tx * 4]);
        float x0 = xs[k][ty * 2 + 0];
        float x1 = xs[k][ty * 2 + 1];
        acc[0][0] += x0 * wv.x; acc[0][1] += x0 * wv.y;
        acc[0][2] += x0 * wv.z; acc[0][3] += x0 * wv.w;
        acc[1][0] += x1 * wv.x; acc[1][1] += x1 * wv.y;
        acc[1][2] += x1 * wv.z; acc[1][3] += x1 * wv.w;
    }
    #pragma unroll
    for (int i = 0; i < 2; i++) {
        int node = nb + ty * 2 + i;
        if (node < NN) {
            __half2 p0 = __floats2half2_rn(acc[i][0], acc[i][1]);
            __half2 p1 = __floats2half2_rn(acc[i][2], acc[i][3]);
            uint2 u;
            u.x = *reinterpret_cast<unsigned*>(&p0);
            u.y = *reinterpret_cast<unsigned*>(&p1);
            reinterpret_cast<uint2*>(g_h2h)[node * 8 + tx] = u;
        }
    }
}

// ---- gather2 + final epilogue. Half-warp per node, half2 loads (64B row). ----
__global__ __launch_bounds__(256) void k_gather2(const float* __restrict__ b2,
                                                 float* __restrict__ out) {
    int gw = (blockIdx.x * 256 + threadIdx.x) >> 5;
    int lane = threadIdx.x & 31;
    int half = lane >> 4, hl = lane & 15;
    int node = gw * 2 + half;
    if (node >= NN) return;
    unsigned hmask = 0xFFFFu << (half * 16);
    int beg = g_rowptr[node], end = g_rowptr[node + 1];
    const __half2* h2 = reinterpret_cast<const __half2*>(g_h2h);

    float2 a0 = {0.f,0.f}, a1 = a0, a2 = a0, a3 = a0;
    for (int c = beg; c < end; c += 16) {
        int idx = c + hl;
        int sreg = (idx < end) ? g_csr_src[idx] : 0;
        int n = end - c; if (n > 16) n = 16;
        int j = 0;
        for (; j + 4 <= n; j += 4) {
            int s0 = __shfl_sync(hmask, sreg, j + 0, 16);
            int s1 = __shfl_sync(hmask, sreg, j + 1, 16);
            int s2 = __shfl_sync(hmask, sreg, j + 2, 16);
            int s3 = __shfl_sync(hmask, sreg, j + 3, 16);
            float2 v0 = __half22float2(h2[s0 * 16 + hl]);
            float2 v1 = __half22float2(h2[s1 * 16 + hl]);
            float2 v2 = __half22float2(h2[s2 * 16 + hl]);
            float2 v3 = __half22float2(h2[s3 * 16 + hl]);
            a0.x += v0.x; a0.y += v0.y;
            a1.x += v1.x; a1.y += v1.y;
            a2.x += v2.x; a2.y += v2.y;
            a3.x += v3.x; a3.y += v3.y;
        }
        for (; j < n; j++) {
            int s = __shfl_sync(hmask, sreg, j, 16);
            float2 v = __half22float2(h2[s * 16 + hl]);
            a0.x += v.x; a0.y += v.y;
        }
    }
    float2 r;
    r.x = (a0.x + a1.x) + (a2.x + a3.x);
    r.y = (a0.y + a1.y) + (a2.y + a3.y);
    float inr = g_innorm[node];
    float2 bb = reinterpret_cast<const float2*>(b2)[hl];
    float2 o;
    o.x = fmaf(r.x, inr, bb.x);
    o.y = fmaf(r.y, inr, bb.y);
    reinterpret_cast<float2*>(out)[node * 16 + hl] = o;
}

extern "C" void kernel_launch(void* const* d_in, const int* in_sizes, int n_in,
                              void* d_out, int out_size) {
    const float* x   = (const float*)d_in[0];
    const int*   src = (const int*)  d_in[1];
    const int*   dst = (const int*)  d_in[2];
    const float* W1  = (const float*)d_in[3];
    const float* b1  = (const float*)d_in[4];
    const float* W2  = (const float*)d_in[5];
    const float* b2  = (const float*)d_in[6];
    float* out = (float*)d_out;

    const int T = 256;
    k_zero     <<<(NN + T - 1) / T, T>>>();
    k_deg      <<<(NE + T - 1) / T, T>>>(src, dst);
    k_scan1    <<<SCAN_NBLK, 256>>>();
    k_scan2    <<<1, 128>>>();
    k_scan3norm<<<(NN + T - 1) / T, T>>>();
    k_bucket   <<<(NE + T - 1) / T, T>>>(src, dst);
    k_gemm1    <<<(NN + 63) / 64, 256>>>(x, W1);
    k_gather1  <<<(NN * 32 + 255) / 256, 256>>>();
    k_gemm2    <<<(NN + 63) / 64, 256>>>(W2, b1);
    k_gather2  <<<(NN * 16 + 255) / 256, 256>>>(b2, out);
}

// round 6
// speedup vs baseline: 1.2626x; 1.2626x over previous
#include <cuda_runtime.h>

#define NN 100000
#define NE 1600000
#define F_IN 64
#define F_HID 64
#define F_OUT 32

#define SCAN_BLK 1024
#define SCAN_NBLK ((NN + SCAN_BLK - 1) / SCAN_BLK)   // 98

// ---- scratch (device globals; no allocation allowed) ----
__device__ float g_h1  [NN * F_HID];   // x@W1 (unscaled)
__device__ float g_h2  [NN * F_OUT];   // layer-2 pre-aggregation features
__device__ float g_outnorm[NN];
__device__ float g_innorm [NN];
__device__ int   g_degs[NN];
__device__ int   g_degd[NN];
__device__ int   g_rowptr[NN + 1];
__device__ int   g_cursor[NN];
__device__ int   g_csr_src[NE];
__device__ int   g_blocksums[SCAN_NBLK];

// ---- zero degree counters ----
__global__ void k_zero() {
    int i = blockIdx.x * blockDim.x + threadIdx.x;
    if (i < NN) { g_degs[i] = 0; g_degd[i] = 0; }
}

// ---- degrees ----
__global__ void k_deg(const int* __restrict__ src, const int* __restrict__ dst) {
    int e = blockIdx.x * blockDim.x + threadIdx.x;
    if (e < NE) {
        atomicAdd(&g_degs[src[e]], 1);
        atomicAdd(&g_degd[dst[e]], 1);
    }
}

// ---- scan stage 1: per-block exclusive scan of dst-degrees ----
__global__ __launch_bounds__(256) void k_scan1() {
    __shared__ int wsum[8];
    int t = threadIdx.x, b = blockIdx.x;
    int base = b * SCAN_BLK + t * 4;
    int v0 = 0, v1 = 0, v2 = 0, v3 = 0;
    if (base + 0 < NN) v0 = g_degd[base + 0];
    if (base + 1 < NN) v1 = g_degd[base + 1];
    if (base + 2 < NN) v2 = g_degd[base + 2];
    if (base + 3 < NN) v3 = g_degd[base + 3];
    int sum = v0 + v1 + v2 + v3;

    int lane = t & 31, wid = t >> 5;
    int x = sum;
    #pragma unroll
    for (int o = 1; o < 32; o <<= 1) {
        int y = __shfl_up_sync(0xffffffffu, x, o);
        if (lane >= o) x += y;
    }
    if (lane == 31) wsum[wid] = x;
    __syncthreads();
    if (wid == 0 && lane < 8) {
        int w = wsum[lane];
        #pragma unroll
        for (int o = 1; o < 8; o <<= 1) {
            int y = __shfl_up_sync(0x000000ffu, w, o);
            if (lane >= o) w += y;
        }
        wsum[lane] = w;
    }
    __syncthreads();
    int incl = x + (wid > 0 ? wsum[wid - 1] : 0);
    int excl = incl - sum;

    if (base + 0 < NN) g_rowptr[base + 0] = excl;
    if (base + 1 < NN) g_rowptr[base + 1] = excl + v0;
    if (base + 2 < NN) g_rowptr[base + 2] = excl + v0 + v1;
    if (base + 3 < NN) g_rowptr[base + 3] = excl + v0 + v1 + v2;
    if (t == 255) g_blocksums[b] = incl;
}

// ---- scan stage 2: exclusive scan of the 98 block sums ----
__global__ __launch_bounds__(128) void k_scan2() {
    __shared__ int wsum[4];
    int t = threadIdx.x;
    int v = (t < SCAN_NBLK) ? g_blocksums[t] : 0;
    int lane = t & 31, wid = t >> 5;
    int x = v;
    #pragma unroll
    for (int o = 1; o < 32; o <<= 1) {
        int y = __shfl_up_sync(0xffffffffu, x, o);
        if (lane >= o) x += y;
    }
    if (lane == 31) wsum[wid] = x;
    __syncthreads();
    if (wid == 0 && lane < 4) {
        int w = wsum[lane];
        #pragma unroll
        for (int o = 1; o < 4; o <<= 1) {
            int y = __shfl_up_sync(0x0000000fu, w, o);
            if (lane >= o) w += y;
        }
        wsum[lane] = w;
    }
    __syncthreads();
    int incl = x + (wid > 0 ? wsum[wid - 1] : 0);
    if (t < SCAN_NBLK) g_blocksums[t] = incl - v;
}

// ---- scan stage 3 + norms ----
__global__ void k_scan3norm() {
    int i = blockIdx.x * blockDim.x + threadIdx.x;
    if (i < NN) {
        int r = g_rowptr[i] + g_blocksums[i >> 10];
        g_rowptr[i] = r;
        g_cursor[i] = r;
        int ds = g_degs[i]; if (ds < 1) ds = 1;
        int dd = g_degd[i]; if (dd < 1) dd = 1;
        g_outnorm[i] = rsqrtf((float)ds);
        g_innorm[i]  = rsqrtf((float)dd);
    }
    if (i == 0) g_rowptr[NN] = NE;
}

// ---- bucket: CSR adjacency (src ids grouped by dst) ----
__global__ void k_bucket(const int* __restrict__ src, const int* __restrict__ dst) {
    int e = blockIdx.x * blockDim.x + threadIdx.x;
    if (e < NE) {
        int pos = atomicAdd(&g_cursor[dst[e]], 1);
        g_csr_src[pos] = src[e];
    }
}

// ---- GEMM1: h1 = x @ W1 (outnorm deferred to gather1) ----
__global__ __launch_bounds__(256) void k_gemm1(const float* __restrict__ x,
                                               const float* __restrict__ W1) {
    __shared__ float Ws[64 * 64];
    __shared__ float xs[64][68];
    int tid = threadIdx.x;
    int nb  = blockIdx.x * 64;

    #pragma unroll
    for (int r = 0; r < 4; r++) {
        int idx = tid + r * 256;
        reinterpret_cast<float4*>(Ws)[idx] =
            reinterpret_cast<const float4*>(W1)[idx];
    }
    #pragma unroll
    for (int r = 0; r < 4; r++) {
        int idx = tid + r * 256;
        int n = idx >> 4, k4 = idx & 15;
        int node = nb + n;
        float4 v = make_float4(0.f, 0.f, 0.f, 0.f);
        if (node < NN)
            v = reinterpret_cast<const float4*>(x)[node * 16 + k4];
        xs[k4 * 4 + 0][n] = v.x;
        xs[k4 * 4 + 1][n] = v.y;
        xs[k4 * 4 + 2][n] = v.z;
        xs[k4 * 4 + 3][n] = v.w;
    }
    __syncthreads();

    int tx = tid & 15;
    int ty = tid >> 4;
    float acc[4][4] = {};
    #pragma unroll
    for (int k = 0; k < 64; k++) {
        float4 wv = *reinterpret_cast<const float4*>(&Ws[k * 64 + tx * 4]);
        float4 xv = *reinterpret_cast<const float4*>(&xs[k][ty * 4]);
        float xr[4] = {xv.x, xv.y, xv.z, xv.w};
        float wr[4] = {wv.x, wv.y, wv.z, wv.w};
        #pragma unroll
        for (int i = 0; i < 4; i++)
            #pragma unroll
            for (int j = 0; j < 4; j++)
                acc[i][j] += xr[i] * wr[j];
    }
    #pragma unroll
    for (int i = 0; i < 4; i++) {
        int node = nb + ty * 4 + i;
        if (node < NN) {
            float4 o = make_float4(acc[i][0], acc[i][1], acc[i][2], acc[i][3]);
            reinterpret_cast<float4*>(g_h1)[node * 16 + tx] = o;
        }
    }
}

// ---- gather1 FUSED: warp/node float2 gather (as R2) + layer-1 epilogue
//      + 64x32 matvec with W2 (smem) -> writes g_h2 directly. ----
__global__ __launch_bounds__(256) void k_gather1f(const float* __restrict__ b1,
                                                  const float* __restrict__ W2) {
    __shared__ float W2s[64 * 32];
    {
        int tid = threadIdx.x;
        #pragma unroll
        for (int r = 0; r < 2; r++) {
            int idx = tid + r * 256;
            reinterpret_cast<float4*>(W2s)[idx] =
                reinterpret_cast<const float4*>(W2)[idx];
        }
    }
    __syncthreads();

    int w = (blockIdx.x * 256 + threadIdx.x) >> 5;
    int lane = threadIdx.x & 31;
    if (w >= NN) return;
    int beg = g_rowptr[w], end = g_rowptr[w + 1];

    float2 a0 = {0.f, 0.f}, a1 = a0, a2 = a0, a3 = a0;
    for (int c = beg; c < end; c += 32) {
        int idx = c + lane;
        int sreg = 0; float snorm = 0.f;
        if (idx < end) { sreg = g_csr_src[idx]; snorm = g_outnorm[sreg]; }
        int n = end - c; if (n > 32) n = 32;
        int j = 0;
        for (; j + 4 <= n; j += 4) {
            int   s0 = __shfl_sync(0xffffffffu, sreg,  j + 0);
            int   s1 = __shfl_sync(0xffffffffu, sreg,  j + 1);
            int   s2 = __shfl_sync(0xffffffffu, sreg,  j + 2);
            int   s3 = __shfl_sync(0xffffffffu, sreg,  j + 3);
            float o0 = __shfl_sync(0xffffffffu, snorm, j + 0);
            float o1 = __shfl_sync(0xffffffffu, snorm, j + 1);
            float o2 = __shfl_sync(0xffffffffu, snorm, j + 2);
            float o3 = __shfl_sync(0xffffffffu, snorm, j + 3);
            float2 v0 = *reinterpret_cast<const float2*>(&g_h1[s0 * 64 + lane * 2]);
            float2 v1 = *reinterpret_cast<const float2*>(&g_h1[s1 * 64 + lane * 2]);
            float2 v2 = *reinterpret_cast<const float2*>(&g_h1[s2 * 64 + lane * 2]);
            float2 v3 = *reinterpret_cast<const float2*>(&g_h1[s3 * 64 + lane * 2]);
            a0.x = fmaf(v0.x, o0, a0.x); a0.y = fmaf(v0.y, o0, a0.y);
            a1.x = fmaf(v1.x, o1, a1.x); a1.y = fmaf(v1.y, o1, a1.y);
            a2.x = fmaf(v2.x, o2, a2.x); a2.y = fmaf(v2.y, o2, a2.y);
            a3.x = fmaf(v3.x, o3, a3.x); a3.y = fmaf(v3.y, o3, a3.y);
        }
        for (; j < n; j++) {
            int   s = __shfl_sync(0xffffffffu, sreg,  j);
            float o = __shfl_sync(0xffffffffu, snorm, j);
            float2 v = *reinterpret_cast<const float2*>(&g_h1[s * 64 + lane * 2]);
            a0.x = fmaf(v.x, o, a0.x); a0.y = fmaf(v.y, o, a0.y);
        }
    }
    float2 r;
    r.x = (a0.x + a1.x) + (a2.x + a3.x);   // agg[2*lane]
    r.y = (a0.y + a1.y) + (a2.y + a3.y);   // agg[2*lane+1]

    // layer-1 epilogue: t = relu(agg*innorm + b1) * outnorm
    float inr = g_innorm[w];
    float onr = g_outnorm[w];
    float2 bb = reinterpret_cast<const float2*>(b1)[lane];
    float2 t;
    t.x = fmaxf(fmaf(r.x, inr, bb.x), 0.f) * onr;
    t.y = fmaxf(fmaf(r.y, inr, bb.y), 0.f) * onr;

    // matvec: h2[w][lane] = sum_k t[k] * W2[k][lane]
    float acc = 0.f;
    #pragma unroll
    for (int k2 = 0; k2 < 32; k2++) {
        float tx = __shfl_sync(0xffffffffu, t.x, k2);
        float ty = __shfl_sync(0xffffffffu, t.y, k2);
        acc = fmaf(tx, W2s[(2 * k2 + 0) * 32 + lane], acc);
        acc = fmaf(ty, W2s[(2 * k2 + 1) * 32 + lane], acc);
    }
    g_h2[w * 32 + lane] = acc;
}

// ---- gather2 + final epilogue: warp/node scalar loads (R2 shape) ----
__global__ __launch_bounds__(256) void k_gather2(const float* __restrict__ b2,
                                                 float* __restrict__ out) {
    int w = (blockIdx.x * blockDim.x + threadIdx.x) >> 5;
    int lane = threadIdx.x & 31;
    if (w >= NN) return;
    int beg = g_rowptr[w], end = g_rowptr[w + 1];

    float a0 = 0.f, a1 = 0.f, a2 = 0.f, a3 = 0.f;
    for (int c = beg; c < end; c += 32) {
        int idx = c + lane;
        int sreg = (idx < end) ? g_csr_src[idx] : 0;
        int n = end - c; if (n > 32) n = 32;
        int j = 0;
        for (; j + 4 <= n; j += 4) {
            int s0 = __shfl_sync(0xffffffffu, sreg, j + 0);
            int s1 = __shfl_sync(0xffffffffu, sreg, j + 1);
            int s2 = __shfl_sync(0xffffffffu, sreg, j + 2);
            int s3 = __shfl_sync(0xffffffffu, sreg, j + 3);
            a0 += g_h2[s0 * 32 + lane];
            a1 += g_h2[s1 * 32 + lane];
            a2 += g_h2[s2 * 32 + lane];
            a3 += g_h2[s3 * 32 + lane];
        }
        for (; j < n; j++) {
            int s = __shfl_sync(0xffffffffu, sreg, j);
            a0 += g_h2[s * 32 + lane];
        }
    }
    float acc = (a0 + a1) + (a2 + a3);
    out[w * 32 + lane] = fmaf(acc, g_innorm[w], b2[lane]);
}

extern "C" void kernel_launch(void* const* d_in, const int* in_sizes, int n_in,
                              void* d_out, int out_size) {
    const float* x   = (const float*)d_in[0];
    const int*   src = (const int*)  d_in[1];
    const int*   dst = (const int*)  d_in[2];
    const float* W1  = (const float*)d_in[3];
    const float* b1  = (const float*)d_in[4];
    const float* W2  = (const float*)d_in[5];
    const float* b2  = (const float*)d_in[6];
    float* out = (float*)d_out;

    const int T = 256;
    k_zero     <<<(NN + T - 1) / T, T>>>();
    k_deg      <<<(NE + T - 1) / T, T>>>(src, dst);
    k_scan1    <<<SCAN_NBLK, 256>>>();
    k_scan2    <<<1, 128>>>();
    k_scan3norm<<<(NN + T - 1) / T, T>>>();
    k_bucket   <<<(NE + T - 1) / T, T>>>(src, dst);
    k_gemm1    <<<(NN + 63) / 64, 256>>>(x, W1);
    k_gather1f <<<(NN * 32 + 255) / 256, 256>>>(b1, W2);
    k_gather2  <<<(NN * 32 + 255) / 256, 256>>>(b2, out);
}

// round 8
// speedup vs baseline: 1.4012x; 1.1097x over previous
#include <cuda_runtime.h>

#define NN 100000
#define NE 1600000
#define F_IN 64
#define F_HID 64
#define F_OUT 32

// ---- scratch (device globals; no allocation allowed) ----
__device__ float g_h1  [NN * F_HID];   // (x@W1)*outnorm
__device__ float g_agg1[NN * F_HID];
__device__ float g_h2  [NN * F_OUT];
__device__ float g_outnorm[NN];
__device__ float g_innorm [NN];
__device__ int   g_degs[NN];
__device__ int   g_degd[NN];
__device__ int   g_rowptr[NN];
__device__ int   g_rowend[NN];
__device__ int   g_cursor[NN];
__device__ int   g_csr_src[NE];
__device__ int   g_total;

// ---- zero degree counters + edge-space counter ----
__global__ void k_zero() {
    int i = blockIdx.x * blockDim.x + threadIdx.x;
    if (i < NN) { g_degs[i] = 0; g_degd[i] = 0; }
    if (i == 0) g_total = 0;
}

// ---- degrees ----
__global__ void k_deg(const int* __restrict__ src, const int* __restrict__ dst) {
    int e = blockIdx.x * blockDim.x + threadIdx.x;
    if (e < NE) {
        atomicAdd(&g_degs[src[e]], 1);
        atomicAdd(&g_degd[dst[e]], 1);
    }
}

// ---- single-kernel range allocation + norms:
//   block-local scan of dst-degrees, block base via one atomicAdd on g_total.
//   Rows get disjoint ranges [rowptr, rowend) in arbitrary global order. ----
__global__ __launch_bounds__(256) void k_scanalloc() {
    __shared__ int wsum[8];
    __shared__ int sbase;
    int t = threadIdx.x;
    int i = blockIdx.x * 256 + t;
    int d = (i < NN) ? g_degd[i] : 0;

    int lane = t & 31, wid = t >> 5;
    int x = d;
    #pragma unroll
    for (int o = 1; o < 32; o <<= 1) {
        int y = __shfl_up_sync(0xffffffffu, x, o);
        if (lane >= o) x += y;
    }
    if (lane == 31) wsum[wid] = x;
    __syncthreads();
    if (wid == 0 && lane < 8) {
        int w = wsum[lane];
        #pragma unroll
        for (int o = 1; o < 8; o <<= 1) {
            int y = __shfl_up_sync(0x000000ffu, w, o);
            if (lane >= o) w += y;
        }
        wsum[lane] = w;
    }
    __syncthreads();
    if (t == 0) sbase = atomicAdd(&g_total, wsum[7]);
    int incl = x + (wid > 0 ? wsum[wid - 1] : 0);
    int excl = incl - d;
    __syncthreads();

    if (i < NN) {
        int r = sbase + excl;
        g_rowptr[i] = r;
        g_cursor[i] = r;
        g_rowend[i] = r + d;
        int ds = g_degs[i]; if (ds < 1) ds = 1;
        int dd = d;         if (dd < 1) dd = 1;
        g_outnorm[i] = rsqrtf((float)ds);
        g_innorm[i]  = rsqrtf((float)dd);
    }
}

// ---- bucket: CSR adjacency (src ids grouped by dst) ----
__global__ void k_bucket(const int* __restrict__ src, const int* __restrict__ dst) {
    int e = blockIdx.x * blockDim.x + threadIdx.x;
    if (e < NE) {
        int pos = atomicAdd(&g_cursor[dst[e]], 1);
        g_csr_src[pos] = src[e];
    }
}

// ---- GEMM1: h1 = (x @ W1) * outnorm.  128-node tile, 128 thr, 8x8/thread. ----
__global__ __launch_bounds__(128) void k_gemm1(const float* __restrict__ x,
                                               const float* __restrict__ W1) {
    __shared__ float Ws[64 * 64];      // 16 KB
    __shared__ float xs[64][128];      // 32 KB  (total 48 KB exactly)
    int tid = threadIdx.x;
    int nb  = blockIdx.x * 128;

    #pragma unroll
    for (int r = 0; r < 8; r++) {
        int idx = tid + r * 128;
        reinterpret_cast<float4*>(Ws)[idx] =
            reinterpret_cast<const float4*>(W1)[idx];
    }
    // Each thread stages its own node row (16 float4, L1-friendly; smem stores
    // conflict-free: fixed k row, n = tid consecutive).
    {
        int node = nb + tid;
        bool ok = node < NN;
        #pragma unroll
        for (int k4 = 0; k4 < 16; k4++) {
            float4 v = make_float4(0.f, 0.f, 0.f, 0.f);
            if (ok) v = reinterpret_cast<const float4*>(x)[node * 16 + k4];
            xs[k4 * 4 + 0][tid] = v.x;
            xs[k4 * 4 + 1][tid] = v.y;
            xs[k4 * 4 + 2][tid] = v.z;
            xs[k4 * 4 + 3][tid] = v.w;
        }
    }
    __syncthreads();

    int tx = tid & 7;        // output group: j0 = tx*8
    int ty = tid >> 3;       // node group:   n0 = ty*8   (0..15)
    int j0 = tx * 8, n0 = ty * 8;
    float acc[8][8] = {};
    #pragma unroll
    for (int k = 0; k < 64; k++) {
        float4 wa = *reinterpret_cast<const float4*>(&Ws[k * 64 + j0]);
        float4 wb = *reinterpret_cast<const float4*>(&Ws[k * 64 + j0 + 4]);
        float4 xa = *reinterpret_cast<const float4*>(&xs[k][n0]);
        float4 xb = *reinterpret_cast<const float4*>(&xs[k][n0 + 4]);
        float wr[8] = {wa.x, wa.y, wa.z, wa.w, wb.x, wb.y, wb.z, wb.w};
        float xr[8] = {xa.x, xa.y, xa.z, xa.w, xb.x, xb.y, xb.z, xb.w};
        #pragma unroll
        for (int i = 0; i < 8; i++)
            #pragma unroll
            for (int j = 0; j < 8; j++)
                acc[i][j] += xr[i] * wr[j];
    }
    #pragma unroll
    for (int i = 0; i < 8; i++) {
        int node = nb + n0 + i;
        if (node < NN) {
            float s = g_outnorm[node];
            float4 o0 = make_float4(acc[i][0] * s, acc[i][1] * s,
                                    acc[i][2] * s, acc[i][3] * s);
            float4 o1 = make_float4(acc[i][4] * s, acc[i][5] * s,
                                    acc[i][6] * s, acc[i][7] * s);
            reinterpret_cast<float4*>(g_h1)[node * 16 + tx * 2 + 0] = o0;
            reinterpret_cast<float4*>(g_h1)[node * 16 + tx * 2 + 1] = o1;
        }
    }
}

// ---- gather1: agg1[n] = sum_s h1[s].  Warp/node, float2 loads (R2 shape). ----
__global__ __launch_bounds__(256) void k_gather1() {
    int w = (blockIdx.x * blockDim.x + threadIdx.x) >> 5;
    int lane = threadIdx.x & 31;
    if (w >= NN) return;
    int beg = g_rowptr[w], end = g_rowend[w];

    float2 a0 = {0.f, 0.f}, a1 = a0, a2 = a0, a3 = a0;
    for (int c = beg; c < end; c += 32) {
        int idx = c + lane;
        int sreg = (idx < end) ? g_csr_src[idx] : 0;
        int n = end - c; if (n > 32) n = 32;
        int j = 0;
        for (; j + 4 <= n; j += 4) {
            int s0 = __shfl_sync(0xffffffffu, sreg, j + 0);
            int s1 = __shfl_sync(0xffffffffu, sreg, j + 1);
            int s2 = __shfl_sync(0xffffffffu, sreg, j + 2);
            int s3 = __shfl_sync(0xffffffffu, sreg, j + 3);
            float2 v0 = *reinterpret_cast<const float2*>(&g_h1[s0 * 64 + lane * 2]);
            float2 v1 = *reinterpret_cast<const float2*>(&g_h1[s1 * 64 + lane * 2]);
            float2 v2 = *reinterpret_cast<const float2*>(&g_h1[s2 * 64 + lane * 2]);
            float2 v3 = *reinterpret_cast<const float2*>(&g_h1[s3 * 64 + lane * 2]);
            a0.x += v0.x; a0.y += v0.y;
            a1.x += v1.x; a1.y += v1.y;
            a2.x += v2.x; a2.y += v2.y;
            a3.x += v3.x; a3.y += v3.y;
        }
        for (; j < n; j++) {
            int s = __shfl_sync(0xffffffffu, sreg, j);
            float2 v = *reinterpret_cast<const float2*>(&g_h1[s * 64 + lane * 2]);
            a0.x += v.x; a0.y += v.y;
        }
    }
    float2 r;
    r.x = (a0.x + a1.x) + (a2.x + a3.x);
    r.y = (a0.y + a1.y) + (a2.y + a3.y);
    reinterpret_cast<float2*>(g_agg1)[w * 32 + lane] = r;
}

// ---- Fused layer-1 epilogue + GEMM2 (64 -> 32), R2 shape ----
__global__ __launch_bounds__(256) void k_gemm2(const float* __restrict__ W2,
                                               const float* __restrict__ b1) {
    __shared__ float Ws[64 * 32];
    __shared__ float xs[64][68];
    int tid = threadIdx.x;
    int nb  = blockIdx.x * 64;

    #pragma unroll
    for (int r = 0; r < 2; r++) {
        int idx = tid + r * 256;
        reinterpret_cast<float4*>(Ws)[idx] =
            reinterpret_cast<const float4*>(W2)[idx];
    }
    #pragma unroll
    for (int r = 0; r < 4; r++) {
        int idx = tid + r * 256;
        int n = idx >> 4, k4 = idx & 15;
        int node = nb + n;
        float4 v = make_float4(0.f, 0.f, 0.f, 0.f);
        if (node < NN) {
            v = reinterpret_cast<const float4*>(g_agg1)[node * 16 + k4];
            float in_n = g_innorm[node];
            float on   = g_outnorm[node];
            float4 bb  = reinterpret_cast<const float4*>(b1)[k4];
            v.x = fmaxf(fmaf(v.x, in_n, bb.x), 0.f) * on;
            v.y = fmaxf(fmaf(v.y, in_n, bb.y), 0.f) * on;
            v.z = fmaxf(fmaf(v.z, in_n, bb.z), 0.f) * on;
            v.w = fmaxf(fmaf(v.w, in_n, bb.w), 0.f) * on;
        }
        xs[k4 * 4 + 0][n] = v.x;
        xs[k4 * 4 + 1][n] = v.y;
        xs[k4 * 4 + 2][n] = v.z;
        xs[k4 * 4 + 3][n] = v.w;
    }
    __syncthreads();

    int tx = tid & 7;
    int ty = tid >> 3;
    float acc[2][4] = {};
    #pragma unroll
    for (int k = 0; k < 64; k++) {
        float4 wv = *reinterpret_cast<const float4*>(&Ws[k * 32 + tx * 4]);
        float x0 = xs[k][ty * 2 + 0];
        float x1 = xs[k][ty * 2 + 1];
        acc[0][0] += x0 * wv.x; acc[0][1] += x0 * wv.y;
        acc[0][2] += x0 * wv.z; acc[0][3] += x0 * wv.w;
        acc[1][0] += x1 * wv.x; acc[1][1] += x1 * wv.y;
        acc[1][2] += x1 * wv.z; acc[1][3] += x1 * wv.w;
    }
    #pragma unroll
    for (int i = 0; i < 2; i++) {
        int node = nb + ty * 2 + i;
        if (node < NN) {
            float4 o = make_float4(acc[i][0], acc[i][1], acc[i][2], acc[i][3]);
            reinterpret_cast<float4*>(g_h2)[node * 8 + tx] = o;
        }
    }
}

// ---- gather2 + final epilogue: warp/node scalar loads (R2 shape) ----
__global__ __launch_bounds__(256) void k_gather2(const float* __restrict__ b2,
                                                 float* __restrict__ out) {
    int w = (blockIdx.x * blockDim.x + threadIdx.x) >> 5;
    int lane = threadIdx.x & 31;
    if (w >= NN) return;
    int beg = g_rowptr[w], end = g_rowend[w];

    float a0 = 0.f, a1 = 0.f, a2 = 0.f, a3 = 0.f;
    for (int c = beg; c < end; c += 32) {
        int idx = c + lane;
        int sreg = (idx < end) ? g_csr_src[idx] : 0;
        int n = end - c; if (n > 32) n = 32;
        int j = 0;
        for (; j + 4 <= n; j += 4) {
            int s0 = __shfl_sync(0xffffffffu, sreg, j + 0);
            int s1 = __shfl_sync(0xffffffffu, sreg, j + 1);
            int s2 = __shfl_sync(0xffffffffu, sreg, j + 2);
            int s3 = __shfl_sync(0xffffffffu, sreg, j + 3);
            a0 += g_h2[s0 * 32 + lane];
            a1 += g_h2[s1 * 32 + lane];
            a2 += g_h2[s2 * 32 + lane];
            a3 += g_h2[s3 * 32 + lane];
        }
        for (; j < n; j++) {
            int s = __shfl_sync(0xffffffffu, sreg, j);
            a0 += g_h2[s * 32 + lane];
        }
    }
    float acc = (a0 + a1) + (a2 + a3);
    out[w * 32 + lane] = fmaf(acc, g_innorm[w], b2[lane]);
}

extern "C" void kernel_launch(void* const* d_in, const int* in_sizes, int n_in,
                              void* d_out, int out_size) {
    const float* x   = (const float*)d_in[0];
    const int*   src = (const int*)  d_in[1];
    const int*   dst = (const int*)  d_in[2];
    const float* W1  = (const float*)d_in[3];
    const float* b1  = (const float*)d_in[4];
    const float* W2  = (const float*)d_in[5];
    const float* b2  = (const float*)d_in[6];
    float* out = (float*)d_out;

    const int T = 256;
    k_zero     <<<(NN + T - 1) / T, T>>>();
    k_deg      <<<(NE + T - 1) / T, T>>>(src, dst);
    k_scanalloc<<<(NN + 255) / 256, 256>>>();
    k_bucket   <<<(NE + T - 1) / T, T>>>(src, dst);
    k_gemm1    <<<(NN + 127) / 128, 128>>>(x, W1);
    k_gather1  <<<(NN * 32 + 255) / 256, 256>>>();
    k_gemm2    <<<(NN + 63) / 64, 256>>>(W2, b1);
    k_gather2  <<<(NN * 32 + 255) / 256, 256>>>(b2, out);
}